// round 1
// baseline (speedup 1.0000x reference)
#include <cuda_runtime.h>
#include <math.h>
#include <stdint.h>

#define B_  64
#define T_  50
#define V_  32000
#define E_  64
#define DH_ 128
#define H_  8
#define M_  256
#define R_  (B_*T_)        // 3200 rows (b*T+t)
#define QKVW_ (3*H_*DH_)   // 3072

// ---------------- scratch (static device allocations only) ----------------
__device__ float g_h[R_*E_];          // embeddings          [3200,64]
__device__ float g_Bqkv[E_*QKVW_];    // packed QKV weight   [64,3072]
__device__ float g_bqkv[QKVW_];       // packed QKV bias     [3072]
__device__ float g_qkv[(size_t)R_*QKVW_]; // QKV activations [3200,3072]
__device__ float g_o[(size_t)R_*H_*DH_];  // attn out concat [3200,1024]
__device__ float g_a[R_*E_];          // after Wo            [3200,64]
__device__ float g_m[R_*M_];          // after gelu          [3200,256]
__device__ float g_y[R_*E_];          // after W2            [3200,64]

// ---------------- embedding ----------------
__global__ void embed_kernel(const int* __restrict__ x,
                             const float* __restrict__ tok,
                             const float* __restrict__ pos,
                             float* __restrict__ h) {
    int idx = blockIdx.x * blockDim.x + threadIdx.x;   // over 3200*64
    if (idx >= R_*E_) return;
    int r = idx >> 6;          // /64
    int e = idx & 63;
    int t = r % T_;
    h[idx] = tok[x[r]*E_ + e] + pos[t*E_ + e];
}

// ---------------- pack QKV weights/bias into [64,3072] GEMM operand --------
__global__ void pack_qkv_kernel(const float* __restrict__ Wq,
                                const float* __restrict__ Wk,
                                const float* __restrict__ Wv,
                                const float* __restrict__ bq,
                                const float* __restrict__ bk,
                                const float* __restrict__ bv,
                                float* __restrict__ Bqkv,
                                float* __restrict__ bias) {
    int idx = blockIdx.x * blockDim.x + threadIdx.x;   // over 64*3072
    if (idx < E_*QKVW_) {
        int e = idx / QKVW_;
        int c = idx - e*QKVW_;
        int m = c >> 10;            // 0:Q 1:K 2:V
        int hd = c & 1023;          // h*128+d
        int hh = hd >> 7;
        int d  = hd & 127;
        const float* W = (m == 0) ? Wq : (m == 1) ? Wk : Wv;
        Bqkv[idx] = W[hh*(E_*DH_) + e*DH_ + d];
    }
    if (idx < QKVW_) {
        bias[idx] = (idx < 1024) ? bq[idx] : (idx < 2048) ? bk[idx-1024] : bv[idx-2048];
    }
}

// ---------------- generic tiled fp32 GEMM: C = A[MxK]*B[KxN] + bias (opt gelu)
template<int BM, int BN, int BK, int TM, int TN, bool GELU>
__global__ void gemm_kernel(const float* __restrict__ A,
                            const float* __restrict__ Bm,
                            const float* __restrict__ bias,
                            float* __restrict__ C,
                            int M, int N, int K) {
    constexpr int THREADS = (BM/TM)*(BN/TN);
    extern __shared__ float sm[];
    float* As = sm;                    // [BK][BM+1] transposed, padded
    float* Bs = sm + BK*(BM+1);        // [BK][BN]

    const int tid = threadIdx.x;
    const int tx  = tid % (BN/TN);
    const int ty  = tid / (BN/TN);
    const int m0  = blockIdx.y * BM;
    const int n0  = blockIdx.x * BN;

    float acc[TM][TN];
#pragma unroll
    for (int i = 0; i < TM; i++)
#pragma unroll
        for (int j = 0; j < TN; j++) acc[i][j] = 0.f;

    for (int k0 = 0; k0 < K; k0 += BK) {
        // A tile (coalesced global read, transposed store, pad-1 => no store conflicts)
#pragma unroll 4
        for (int idx = tid; idx < BM*BK; idx += THREADS) {
            int m = idx / BK, k = idx - m*BK;
            As[k*(BM+1) + m] = A[(size_t)(m0+m)*K + k0 + k];
        }
        // B tile, float4 coalesced
#pragma unroll 4
        for (int idx = tid*4; idx < BK*BN; idx += THREADS*4) {
            int k = idx / BN, n = idx - k*BN;
            *(float4*)&Bs[k*BN + n] = *(const float4*)&Bm[(size_t)(k0+k)*N + n0 + n];
        }
        __syncthreads();

#pragma unroll 8
        for (int k = 0; k < BK; k++) {
            float a[TM];
#pragma unroll
            for (int i = 0; i < TM; i++) a[i] = As[k*(BM+1) + ty*TM + i]; // warp broadcast
            float4 bv4 = *(float4*)&Bs[k*BN + tx*TN];                     // conflict-free
            float b[4] = {bv4.x, bv4.y, bv4.z, bv4.w};
#pragma unroll
            for (int i = 0; i < TM; i++)
#pragma unroll
                for (int j = 0; j < TN; j++)
                    acc[i][j] = fmaf(a[i], b[j], acc[i][j]);
        }
        __syncthreads();
    }

    float4 bb = *(const float4*)&bias[n0 + tx*TN];
    float bv[4] = {bb.x, bb.y, bb.z, bb.w};
#pragma unroll
    for (int i = 0; i < TM; i++) {
        float v[4];
#pragma unroll
        for (int j = 0; j < TN; j++) {
            float xv = acc[i][j] + bv[j];
            if (GELU) xv = 0.5f * xv * (1.f + erff(xv * 0.7071067811865476f));
            v[j] = xv;
        }
        float4 outv = {v[0], v[1], v[2], v[3]};
        *(float4*)&C[(size_t)(m0 + ty*TM + i)*N + n0 + tx*TN] = outv;
    }
}

template<int BM, int BN, int BK, int TM, int TN, bool GELU>
static void launch_gemm(const float* A, const float* Bm, const float* bias,
                        float* C, int M, int N, int K) {
    constexpr int THREADS = (BM/TM)*(BN/TN);
    size_t smem = (size_t)(BK*(BM+1) + BK*BN) * sizeof(float);
    cudaFuncSetAttribute(gemm_kernel<BM,BN,BK,TM,TN,GELU>,
                         cudaFuncAttributeMaxDynamicSharedMemorySize, (int)smem);
    dim3 grid(N/BN, M/BM);
    gemm_kernel<BM,BN,BK,TM,TN,GELU><<<grid, THREADS, smem>>>(A, Bm, bias, C, M, N, K);
}

// ---------------- attention: one block per (b,h), whole [50,128] tile -------
// smem: Qs[50*128] | KsT[128*52] | Vs[50*128] | Ss[50*52]
__global__ void attn_kernel(const float* __restrict__ qkv, float* __restrict__ o) {
    extern __shared__ float sm[];
    float* Qs  = sm;                 // 6400
    float* KsT = sm + 6400;          // 128*52 = 6656 (transposed for conflict-free dot)
    float* Vs  = sm + 13056;         // 6400
    float* Ss  = sm + 19456;         // 50*52 = 2600

    const int bh = blockIdx.x;
    const int b  = bh / H_;
    const int h  = bh % H_;
    const int tid = threadIdx.x;

    const float* base = qkv + (size_t)b * T_ * QKVW_ + h * DH_;

    for (int idx = tid; idx < T_*DH_; idx += blockDim.x) {
        int t = idx >> 7;
        int d = idx & 127;
        const float* row = base + (size_t)t * QKVW_;
        Qs[t*DH_ + d]   = row[d];
        KsT[d*52 + t]   = row[1024 + d];
        Vs[t*DH_ + d]   = row[2048 + d];
    }
    __syncthreads();

    // scores (causal only), warp per query row, lanes over keys
    const int warp = tid >> 5, lane = tid & 31;
    const float scale = 0.08838834764831845f;   // 1/sqrt(128)
    for (int t = warp; t < T_; t += (blockDim.x >> 5)) {
        for (int s = lane; s <= t; s += 32) {
            float acc = 0.f;
#pragma unroll 8
            for (int k = 0; k < DH_; k++)
                acc = fmaf(Qs[t*DH_ + k], KsT[k*52 + s], acc);
            Ss[t*52 + s] = acc * scale;
        }
    }
    __syncthreads();

    // softmax, one thread per row (rows tiny)
    for (int t = tid; t < T_; t += blockDim.x) {
        float mx = -INFINITY;
        for (int s = 0; s <= t; s++) mx = fmaxf(mx, Ss[t*52 + s]);
        float sum = 0.f;
        for (int s = 0; s <= t; s++) {
            float e = expf(Ss[t*52 + s] - mx);
            Ss[t*52 + s] = e;
            sum += e;
        }
        float inv = 1.f / sum;
        for (int s = 0; s <= t; s++) Ss[t*52 + s] *= inv;
    }
    __syncthreads();

    // o = attn @ V, lanes over d (Vs conflict-free, Ss broadcast)
    for (int idx = tid; idx < T_*DH_; idx += blockDim.x) {
        int t = idx >> 7;
        int d = idx & 127;
        float acc = 0.f;
        for (int s = 0; s <= t; s++)
            acc = fmaf(Ss[t*52 + s], Vs[s*DH_ + d], acc);
        o[(size_t)(b*T_ + t) * (H_*DH_) + h*DH_ + d] = acc;
    }
}

// ---------------- launch ----------------
extern "C" void kernel_launch(void* const* d_in, const int* in_sizes, int n_in,
                              void* d_out, int out_size) {
    (void)in_sizes; (void)n_in; (void)out_size;
    const int*   x   = (const int*)  d_in[0];
    const float* tok = (const float*)d_in[1];
    const float* pos = (const float*)d_in[2];
    const float* Wq  = (const float*)d_in[3];
    const float* bq  = (const float*)d_in[4];
    const float* Wk  = (const float*)d_in[5];
    const float* bk  = (const float*)d_in[6];
    const float* Wv  = (const float*)d_in[7];
    const float* bv  = (const float*)d_in[8];
    const float* Wo  = (const float*)d_in[9];
    const float* bo  = (const float*)d_in[10];
    const float* W1  = (const float*)d_in[11];
    const float* b1  = (const float*)d_in[12];
    const float* W2  = (const float*)d_in[13];
    const float* b2  = (const float*)d_in[14];
    const float* Wf  = (const float*)d_in[15];
    const float* bf  = (const float*)d_in[16];
    float* out = (float*)d_out;

    float *h, *Bqkv, *bqkv, *qkv, *o, *a, *m, *y;
    cudaGetSymbolAddress((void**)&h,    g_h);
    cudaGetSymbolAddress((void**)&Bqkv, g_Bqkv);
    cudaGetSymbolAddress((void**)&bqkv, g_bqkv);
    cudaGetSymbolAddress((void**)&qkv,  g_qkv);
    cudaGetSymbolAddress((void**)&o,    g_o);
    cudaGetSymbolAddress((void**)&a,    g_a);
    cudaGetSymbolAddress((void**)&m,    g_m);
    cudaGetSymbolAddress((void**)&y,    g_y);

    // 1) embeddings
    embed_kernel<<<(R_*E_ + 255)/256, 256>>>(x, tok, pos, h);
    // 2) pack QKV weights into a single [64,3072] operand
    pack_qkv_kernel<<<(E_*QKVW_ + 255)/256, 256>>>(Wq, Wk, Wv, bq, bk, bv, Bqkv, bqkv);
    // 3) QKV projection: [3200,64] x [64,3072]
    launch_gemm<64,128,64,8,4,false>(h, Bqkv, bqkv, qkv, R_, QKVW_, E_);
    // 4) attention: 512 blocks of (b,h)
    {
        size_t smem = (size_t)(6400 + 6656 + 6400 + 2600) * sizeof(float); // 88224 B
        cudaFuncSetAttribute(attn_kernel, cudaFuncAttributeMaxDynamicSharedMemorySize, (int)smem);
        attn_kernel<<<B_*H_, 256, smem>>>(qkv, o);
    }
    // 5) output projection: [3200,1024] x [1024,64]
    launch_gemm<64,64,32,4,4,false>(o, Wo, bo, a, R_, E_, H_*DH_);
    // 6) MLP up + exact GELU: [3200,64] x [64,256]
    launch_gemm<64,64,64,4,4,true >(a, W1, b1, m, R_, M_, E_);
    // 7) MLP down: [3200,256] x [256,64]
    launch_gemm<64,64,64,4,4,false>(m, W2, b2, y, R_, E_, M_);
    // 8) final logits: [3200,64] x [64,32000]  (dominant)
    launch_gemm<64,128,64,8,4,false>(y, Wf, bf, out, R_, V_, E_);
}

// round 4
// speedup vs baseline: 1.0572x; 1.0572x over previous
#include <cuda_runtime.h>
#include <math.h>
#include <stdint.h>

#define B_  64
#define T_  50
#define V_  32000
#define E_  64
#define DH_ 128
#define H_  8
#define M_  256
#define R_  (B_*T_)        // 3200 rows (b*T+t)
#define QKVW_ (3*H_*DH_)   // 3072

// ---------------- scratch (static device allocations only) ----------------
__device__ float g_h[R_*E_];          // embeddings          [3200,64]
__device__ float g_Bqkv[E_*QKVW_];    // packed QKV weight   [64,3072]
__device__ float g_bqkv[QKVW_];       // packed QKV bias     [3072]
__device__ float g_qkv[(size_t)R_*QKVW_]; // QKV activations [3200,3072]
__device__ float g_o[(size_t)R_*H_*DH_];  // attn out concat [3200,1024]
__device__ float g_a[R_*E_];          // after Wo            [3200,64]
__device__ float g_m[R_*M_];          // after gelu          [3200,256]
__device__ float g_y[R_*E_];          // after W2            [3200,64]

// ---------------- packed fp32x2 FMA (sm_103a FFMA2) ----------------
__device__ __forceinline__ float2 ffma2(float2 a, float2 b, float2 c) {
    unsigned long long au = *reinterpret_cast<unsigned long long*>(&a);
    unsigned long long bu = *reinterpret_cast<unsigned long long*>(&b);
    unsigned long long cu = *reinterpret_cast<unsigned long long*>(&c);
    unsigned long long du;
    asm("fma.rn.f32x2 %0, %1, %2, %3;" : "=l"(du) : "l"(au), "l"(bu), "l"(cu));
    return *reinterpret_cast<float2*>(&du);
}

// ---------------- embedding ----------------
__global__ void embed_kernel(const int* __restrict__ x,
                             const float* __restrict__ tok,
                             const float* __restrict__ pos,
                             float* __restrict__ h) {
    int idx = blockIdx.x * blockDim.x + threadIdx.x;   // over 3200*64
    if (idx >= R_*E_) return;
    int r = idx >> 6;          // /64
    int e = idx & 63;
    int t = r % T_;
    h[idx] = tok[x[r]*E_ + e] + pos[t*E_ + e];
}

// ---------------- pack QKV weights/bias into [64,3072] GEMM operand --------
__global__ void pack_qkv_kernel(const float* __restrict__ Wq,
                                const float* __restrict__ Wk,
                                const float* __restrict__ Wv,
                                const float* __restrict__ bq,
                                const float* __restrict__ bk,
                                const float* __restrict__ bv,
                                float* __restrict__ Bqkv,
                                float* __restrict__ bias) {
    int idx = blockIdx.x * blockDim.x + threadIdx.x;   // over 64*3072
    if (idx < E_*QKVW_) {
        int e = idx / QKVW_;
        int c = idx - e*QKVW_;
        int m = c >> 10;            // 0:Q 1:K 2:V
        int hd = c & 1023;          // h*128+d
        int hh = hd >> 7;
        int d  = hd & 127;
        const float* W = (m == 0) ? Wq : (m == 1) ? Wk : Wv;
        Bqkv[idx] = W[hh*(E_*DH_) + e*DH_ + d];
    }
    if (idx < QKVW_) {
        bias[idx] = (idx < 1024) ? bq[idx] : (idx < 2048) ? bk[idx-1024] : bv[idx-2048];
    }
}

// ---------------- tiled fp32 GEMM with FFMA2 (pairs along M) ----------------
// C = A[MxK]*B[KxN] + bias (optional exact GELU). TM, TN multiples of 2/4.
template<int BM, int BN, int BK, int TM, int TN, bool GELU>
__global__ void gemm_kernel(const float* __restrict__ A,
                            const float* __restrict__ Bm,
                            const float* __restrict__ bias,
                            float* __restrict__ C,
                            int M, int N, int K) {
    constexpr int THREADS = (BM/TM)*(BN/TN);
    constexpr int AS = BM + 2;          // even stride: float2-aligned, 2-way store conflict only
    extern __shared__ float sm[];
    float* As = sm;                     // [BK][AS] transposed
    float* Bs = sm + BK*AS;             // [BK][BN]

    const int tid = threadIdx.x;
    const int tx  = tid % (BN/TN);
    const int ty  = tid / (BN/TN);
    const int m0  = blockIdx.y * BM;
    const int n0  = blockIdx.x * BN;

    float2 acc[TM/2][TN];
#pragma unroll
    for (int i = 0; i < TM/2; i++)
#pragma unroll
        for (int j = 0; j < TN; j++) acc[i][j] = make_float2(0.f, 0.f);

    for (int k0 = 0; k0 < K; k0 += BK) {
        // A tile: coalesced global read, transposed store
#pragma unroll 4
        for (int idx = tid; idx < BM*BK; idx += THREADS) {
            int m = idx / BK, k = idx - m*BK;
            As[k*AS + m] = A[(size_t)(m0+m)*K + k0 + k];
        }
        // B tile: float4 coalesced
#pragma unroll 4
        for (int idx = tid*4; idx < BK*BN; idx += THREADS*4) {
            int k = idx / BN, n = idx - k*BN;
            *(float4*)&Bs[k*BN + n] = *(const float4*)&Bm[(size_t)(k0+k)*N + n0 + n];
        }
        __syncthreads();

#pragma unroll 8
        for (int k = 0; k < BK; k++) {
            // a: pairs along m, contiguous in As (LDS.64, warp-broadcast)
            float2 a2[TM/2];
#pragma unroll
            for (int i = 0; i < TM/2; i++)
                a2[i] = *(float2*)&As[k*AS + ty*TM + 2*i];
            // b: TN scalars (LDS.128 conflict-free), duplicate per lane-pair
            float4 bv4 = *(float4*)&Bs[k*BN + tx*TN];
            float bsc[4] = {bv4.x, bv4.y, bv4.z, bv4.w};
#pragma unroll
            for (int j = 0; j < TN; j++) {
                float2 bd = make_float2(bsc[j], bsc[j]);
#pragma unroll
                for (int i = 0; i < TM/2; i++)
                    acc[i][j] = ffma2(a2[i], bd, acc[i][j]);
            }
        }
        __syncthreads();
    }

    float4 bb = *(const float4*)&bias[n0 + tx*TN];
    float bv[4] = {bb.x, bb.y, bb.z, bb.w};
#pragma unroll
    for (int i = 0; i < TM/2; i++) {
#pragma unroll
        for (int half = 0; half < 2; half++) {
            float v[4];
#pragma unroll
            for (int j = 0; j < TN; j++) {
                float xv = (half == 0 ? acc[i][j].x : acc[i][j].y) + bv[j];
                if (GELU) xv = 0.5f * xv * (1.f + erff(xv * 0.7071067811865476f));
                v[j] = xv;
            }
            float4 outv = {v[0], v[1], v[2], v[3]};
            *(float4*)&C[(size_t)(m0 + ty*TM + 2*i + half)*N + n0 + tx*TN] = outv;
        }
    }
}

template<int BM, int BN, int BK, int TM, int TN, bool GELU>
static void launch_gemm(const float* A, const float* Bm, const float* bias,
                        float* C, int M, int N, int K) {
    constexpr int THREADS = (BM/TM)*(BN/TN);
    size_t smem = (size_t)(BK*(BM+2) + BK*BN) * sizeof(float);
    cudaFuncSetAttribute(gemm_kernel<BM,BN,BK,TM,TN,GELU>,
                         cudaFuncAttributeMaxDynamicSharedMemorySize, (int)smem);
    dim3 grid(N/BN, M/BM);
    gemm_kernel<BM,BN,BK,TM,TN,GELU><<<grid, THREADS, smem>>>(A, Bm, bias, C, M, N, K);
}

// ---------------- attention: one block per (b,h) --------------------------
// smem: Ks[50][132] | Vs[50][132] | Ss[50][52]   (63.2 KB -> 3 CTAs/SM)
#define KVS_ 132
__global__ void attn_kernel(const float* __restrict__ qkv, float* __restrict__ o) {
    extern __shared__ float sm[];
    float* Ks = sm;                    // 50*132 = 6600
    float* Vs = sm + T_*KVS_;          // 6600
    float* Ss = sm + 2*T_*KVS_;        // 50*52 = 2600

    const int bh = blockIdx.x;
    const int b  = bh / H_;
    const int h  = bh % H_;
    const int tid = threadIdx.x;

    const float* base = qkv + (size_t)b * T_ * QKVW_ + h * DH_;

    // stage K and V (coalesced float4 reads, padded rows for conflict-free LDS.128)
    for (int idx = tid; idx < T_*(DH_/4); idx += blockDim.x) {
        int t = idx >> 5;            // / 32
        int dq = idx & 31;
        const float* row = base + (size_t)t * QKVW_;
        *(float4*)&Ks[t*KVS_ + 4*dq] = *(const float4*)&row[1024 + 4*dq];
        *(float4*)&Vs[t*KVS_ + 4*dq] = *(const float4*)&row[2048 + 4*dq];
    }
    __syncthreads();

    // scores (causal only): warp per query row, lanes over keys, FFMA2 over k
    const int warp = tid >> 5, lane = tid & 31;
    const int nwarp = blockDim.x >> 5;
    const float scale = 0.08838834764831845f;   // 1/sqrt(128)
    for (int t = warp; t < T_; t += nwarp) {
        const float* qg = base + (size_t)t * QKVW_;   // Q row (global, L1, uniform)
        for (int s = lane; s <= t; s += 32) {
            float2 acc0 = make_float2(0.f, 0.f);
            float2 acc1 = make_float2(0.f, 0.f);
#pragma unroll 8
            for (int k = 0; k < DH_; k += 4) {
                float4 q4 = *(const float4*)&qg[k];
                float4 k4 = *(float4*)&Ks[s*KVS_ + k];
                acc0 = ffma2(make_float2(q4.x, q4.y), make_float2(k4.x, k4.y), acc0);
                acc1 = ffma2(make_float2(q4.z, q4.w), make_float2(k4.z, k4.w), acc1);
            }
            Ss[t*52 + s] = (acc0.x + acc0.y + acc1.x + acc1.y) * scale;
        }
    }
    __syncthreads();

    // softmax, one thread per row (rows tiny)
    for (int t = tid; t < T_; t += blockDim.x) {
        float mx = -INFINITY;
        for (int s = 0; s <= t; s++) mx = fmaxf(mx, Ss[t*52 + s]);
        float sum = 0.f;
        for (int s = 0; s <= t; s++) {
            float e = expf(Ss[t*52 + s] - mx);
            Ss[t*52 + s] = e;
            sum += e;
        }
        float inv = 1.f / sum;
        for (int s = 0; s <= t; s++) Ss[t*52 + s] *= inv;
    }
    __syncthreads();

    // o = attn @ V: thread per (t, d-quad); p broadcast, V LDS.128, FFMA2
    for (int idx = tid; idx < T_*(DH_/4); idx += blockDim.x) {
        int t  = idx >> 5;
        int dq = idx & 31;
        float2 acc0 = make_float2(0.f, 0.f);
        float2 acc1 = make_float2(0.f, 0.f);
        for (int s = 0; s <= t; s++) {
            float p = Ss[t*52 + s];
            float2 pd = make_float2(p, p);
            float4 v4 = *(float4*)&Vs[s*KVS_ + 4*dq];
            acc0 = ffma2(pd, make_float2(v4.x, v4.y), acc0);
            acc1 = ffma2(pd, make_float2(v4.z, v4.w), acc1);
        }
        float4 outv = {acc0.x, acc0.y, acc1.x, acc1.y};
        *(float4*)&o[(size_t)(b*T_ + t) * (H_*DH_) + h*DH_ + 4*dq] = outv;
    }
}

// ---------------- launch ----------------
extern "C" void kernel_launch(void* const* d_in, const int* in_sizes, int n_in,
                              void* d_out, int out_size) {
    (void)in_sizes; (void)n_in; (void)out_size;
    const int*   x   = (const int*)  d_in[0];
    const float* tok = (const float*)d_in[1];
    const float* pos = (const float*)d_in[2];
    const float* Wq  = (const float*)d_in[3];
    const float* bq  = (const float*)d_in[4];
    const float* Wk  = (const float*)d_in[5];
    const float* bk  = (const float*)d_in[6];
    const float* Wv  = (const float*)d_in[7];
    const float* bv  = (const float*)d_in[8];
    const float* Wo  = (const float*)d_in[9];
    const float* bo  = (const float*)d_in[10];
    const float* W1  = (const float*)d_in[11];
    const float* b1  = (const float*)d_in[12];
    const float* W2  = (const float*)d_in[13];
    const float* b2  = (const float*)d_in[14];
    const float* Wf  = (const float*)d_in[15];
    const float* bf  = (const float*)d_in[16];
    float* out = (float*)d_out;

    float *h, *Bqkv, *bqkv, *qkv, *o, *a, *m, *y;
    cudaGetSymbolAddress((void**)&h,    g_h);
    cudaGetSymbolAddress((void**)&Bqkv, g_Bqkv);
    cudaGetSymbolAddress((void**)&bqkv, g_bqkv);
    cudaGetSymbolAddress((void**)&qkv,  g_qkv);
    cudaGetSymbolAddress((void**)&o,    g_o);
    cudaGetSymbolAddress((void**)&a,    g_a);
    cudaGetSymbolAddress((void**)&m,    g_m);
    cudaGetSymbolAddress((void**)&y,    g_y);

    // 1) embeddings
    embed_kernel<<<(R_*E_ + 255)/256, 256>>>(x, tok, pos, h);
    // 2) pack QKV weights into a single [64,3072] operand
    pack_qkv_kernel<<<(E_*QKVW_ + 255)/256, 256>>>(Wq, Wk, Wv, bq, bk, bv, Bqkv, bqkv);
    // 3) QKV projection: [3200,64] x [64,3072]
    launch_gemm<64,128,64,8,4,false>(h, Bqkv, bqkv, qkv, R_, QKVW_, E_);
    // 4) attention: 512 blocks of (b,h)
    {
        size_t smem = (size_t)(2*T_*KVS_ + T_*52) * sizeof(float);   // 63.2 KB
        cudaFuncSetAttribute(attn_kernel, cudaFuncAttributeMaxDynamicSharedMemorySize, (int)smem);
        attn_kernel<<<B_*H_, 256, smem>>>(qkv, o);
    }
    // 5) output projection: [3200,1024] x [1024,64]
    launch_gemm<64,64,32,4,4,false>(o, Wo, bo, a, R_, E_, H_*DH_);
    // 6) MLP up + exact GELU: [3200,64] x [64,256]
    launch_gemm<64,64,64,4,4,true >(a, W1, b1, m, R_, M_, E_);
    // 7) MLP down: [3200,256] x [256,64]
    launch_gemm<64,64,64,4,4,false>(m, W2, b2, y, R_, E_, M_);
    // 8) final logits: [3200,64] x [64,32000]  (dominant)
    launch_gemm<64,128,64,8,4,false>(y, Wf, bf, out, R_, V_, E_);
}